// round 7
// baseline (speedup 1.0000x reference)
#include <cuda_runtime.h>
#include <math.h>

#define NN 8
#define HH 12
#define DHD 64
#define LV 1568
#define LA 512
#define NCV 392
#define NCA 256
#define NHNH (NN*HH)          // 96
#define OSTR 5696             // output row stride
#define RS_V 8                // row-splits for v_pos accumulation (256/8 = 32 rows per block)
#define RS_A 8                // row-splits for a_pos accumulation (392/8 = 49 rows per block)
#define SCALEF 0.125f

#define K1_BLOCKS (2 * RS_V * NHNH)   // 1536
#define K2_BLOCKS (RS_A * NHNH)       // 768

// ---- scratch (device globals; no allocation allowed) ----
__device__ float g_w_av[NN * NCV];
__device__ float g_w_va[NN * NCA];
__device__ float g_sum_av[NN];
__device__ float g_sum_va[NN];
__device__ float g_vpos[RS_V * NHNH * LV];   // partial accumulators, full LV columns
__device__ float g_apos[RS_A * NHNH * LA];   // partial accumulators, full LA columns

// K0: gather weights, compute their sums, fill output defaults (prob=0, prune=n_attn)
__global__ void k0_prep(const float* __restrict__ n_attn_av,
                        const float* __restrict__ n_attn_va,
                        const int* __restrict__ ids_v,
                        const int* __restrict__ ids_a,
                        float* __restrict__ out) {
    int n = blockIdx.x;
    int t = threadIdx.x;             // 512 threads
    __shared__ float red[512];

    float wv = 0.f;
    if (t < NCV) {
        int p = ids_v[n * LV + t];
        wv = n_attn_av[n * LV + p];
        g_w_av[n * NCV + t] = wv;
    }
    red[t] = wv;
    __syncthreads();
    for (int s = 256; s > 0; s >>= 1) {
        if (t < s) red[t] += red[t + s];
        __syncthreads();
    }
    if (t == 0) g_sum_av[n] = red[0];
    __syncthreads();

    float wa = 0.f;
    if (t < NCA) {
        int p = ids_a[n * LA + t];
        wa = n_attn_va[n * LA + p];
        g_w_va[n * NCA + t] = wa;
    }
    red[t] = wa;
    __syncthreads();
    for (int s = 256; s > 0; s >>= 1) {
        if (t < s) red[t] += red[t + s];
        __syncthreads();
    }
    if (t == 0) g_sum_va[n] = red[0];

    // output defaults
    float* o = out + n * OSTR;
    for (int i = t; i < LV + LA; i += 512) o[i] = 0.f;                       // prob regions
    for (int i = t; i < LV; i += 512) o[3616 + i] = n_attn_av[n * LV + i];   // prune_av default
    for (int i = t; i < LA; i += 512) o[5184 + i] = n_attn_va[n * LA + i];   // prune_va default
}

// K12 fused: streaming weighted row-sums for both cross tensors.
// blocks [0, K1_BLOCKS): v_pos partials from cross_av (float4 lanes)
// blocks [K1_BLOCKS, K1_BLOCKS+K2_BLOCKS): a_pos partials from cross_va (float2 lanes)
__global__ void k12_stream(const float* __restrict__ cross_av,
                           const float* __restrict__ cross_va,
                           const int* __restrict__ ids_a,
                           const int* __restrict__ ids_v) {
    const int bid = blockIdx.x;
    const int t = threadIdx.x;   // 256

    if (bid < K1_BLOCKS) {
        const int x = bid & 1;
        const int y = (bid >> 1) & (RS_V - 1);
        const int nh = bid >> 4;
        const int n = nh / HH;
        const int g = x * 256 + t;                 // float4 column group (LV/4 = 392)
        const int RPB = NCA / RS_V;                // 32 rows per block

        __shared__ int   ridx[NCA / RS_V];
        __shared__ float rw[NCA / RS_V];
        if (t < RPB) {
            int a = y * RPB + t;
            ridx[t] = ids_a[n * LA + a];
            rw[t]   = g_w_va[n * NCA + a];
        }
        __syncthreads();
        if (g >= LV / 4) return;

        float4 acc = make_float4(0.f, 0.f, 0.f, 0.f);
        const float4* base = (const float4*)cross_av;
        const size_t nhbase = (size_t)nh * LA * (LV / 4);
#pragma unroll 8
        for (int a = 0; a < RPB; a++) {
            float w = rw[a];
            float4 v = __ldg(base + nhbase + (size_t)ridx[a] * (LV / 4) + g);
            acc.x += w * v.x; acc.y += w * v.y; acc.z += w * v.z; acc.w += w * v.w;
        }
        ((float4*)g_vpos)[(size_t)(y * NHNH + nh) * (LV / 4) + g] = acc;
    } else {
        const int b2 = bid - K1_BLOCKS;
        const int y = b2 & (RS_A - 1);
        const int nh = b2 >> 3;
        const int n = nh / HH;
        const int RPB = NCV / RS_A;                // 49 rows per block

        __shared__ int   ridx2[NCV / RS_A];
        __shared__ float rw2[NCV / RS_A];
        if (t < RPB) {
            int v = y * RPB + t;
            ridx2[t] = ids_v[n * LV + v];
            rw2[t]   = g_w_av[n * NCV + v];
        }
        __syncthreads();

        float2 acc = make_float2(0.f, 0.f);
        const float2* base = (const float2*)cross_va;
        const size_t nhbase = (size_t)nh * LV * (LA / 2);
#pragma unroll 7
        for (int a = 0; a < RPB; a++) {
            float w = rw2[a];
            float2 v = __ldg(base + nhbase + (size_t)ridx2[a] * (LA / 2) + t);
            acc.x += w * v.x; acc.y += w * v.y;
        }
        ((float2*)g_apos)[(size_t)(y * NHNH + nh) * (LA / 2) + t] = acc;
    }
}

// K3: pos_v_cls / pos_a_cls: weighted mean over gathered rows of pos_*_q
// 1024 threads = 16 sub-groups x 64 lanes; sub-group s handles rows s, s+16, ...
__global__ void k3_cls(const float* __restrict__ pos_v_q,
                       const float* __restrict__ pos_a_q,
                       const int* __restrict__ ids_v,
                       const int* __restrict__ ids_a,
                       float* __restrict__ out) {
    const int nh = blockIdx.x;
    const int n = nh / HH;
    const int h = nh % HH;
    const int d = threadIdx.x & 63;      // headdim lane
    const int sub = threadIdx.x >> 6;    // 0..15
    const bool vside = (blockIdx.y == 0);

    __shared__ int   ridx[NCV];
    __shared__ float rw[NCV];
    __shared__ float part[16 * DHD];

    const int cnt = vside ? NCV : NCA;
    const int L = vside ? LV : LA;
    const int* ids = vside ? ids_v : ids_a;
    const float* wsrc = vside ? (g_w_av + n * NCV) : (g_w_va + n * NCA);
    const float* q = vside ? pos_v_q : pos_a_q;

    for (int i = threadIdx.x; i < cnt; i += 1024) {
        ridx[i] = ids[n * L + i];
        rw[i]   = wsrc[i];
    }
    __syncthreads();

    float acc = 0.f;
    const float* basep = q + (size_t)nh * L * DHD;
#pragma unroll 8
    for (int i = sub; i < cnt; i += 16)
        acc += __ldg(basep + (size_t)ridx[i] * DHD + d) * rw[i];

    part[sub * DHD + d] = acc;
    __syncthreads();

    if (sub == 0) {
        float tot = acc;
#pragma unroll
        for (int s = 1; s < 16; s++) tot += part[s * DHD + d];
        const float su = vside ? g_sum_av[n] : g_sum_va[n];
        const int off = vside ? 2080 : 2848;
        out[n * OSTR + off + h * DHD + d] = tot / su;
    }
}

// K45 fused: per-token prob for both sides.
// blockIdx.x < NCV -> v-side token, else a-side token (l = blockIdx.x - NCV).
__global__ void k45_prob(const float* __restrict__ pos_v_k,
                         const float* __restrict__ pos_a_k,
                         const float* __restrict__ spu_a_cls,
                         const float* __restrict__ spu_v_cls,
                         const int* __restrict__ ids_v,
                         const int* __restrict__ ids_a,
                         const float* __restrict__ u_v,
                         const float* __restrict__ u_a,
                         const float* __restrict__ n_attn_av,
                         const float* __restrict__ n_attn_va,
                         float* __restrict__ out) {
    const int n = blockIdx.y;
    const bool vside = (blockIdx.x < NCV);
    const int l = vside ? blockIdx.x : blockIdx.x - NCV;
    const int h = threadIdx.x >> 5;
    const int lane = threadIdx.x & 31;

    const int L = vside ? LV : LA;
    const int* ids = vside ? ids_v : ids_a;
    const float* kk = vside ? pos_v_k : pos_a_k;
    const float* cls = vside ? spu_a_cls : spu_v_cls;

    __shared__ int s_row;
    __shared__ float s_sig[HH];
    if (threadIdx.x == 0) s_row = ids[n * L + l];
    __syncthreads();
    const int row = s_row;
    const int nh = n * HH + h;

    const float2* kr = (const float2*)(kk + ((size_t)nh * L + row) * DHD);
    const float2* cr = (const float2*)(cls + (size_t)nh * DHD);
    float2 a = __ldg(kr + lane);
    float2 b = __ldg(cr + lane);
    float p = a.x * b.x + a.y * b.y;
#pragma unroll
    for (int s = 16; s > 0; s >>= 1) p += __shfl_xor_sync(0xffffffff, p, s);

    if (lane == 0) {
        float spu = p * SCALEF;
        float vp = 0.f;
        if (vside) {
#pragma unroll
            for (int y = 0; y < RS_V; y++) vp += g_vpos[(size_t)(y * NHNH + nh) * LV + row];
            vp /= g_sum_va[n];
        } else {
#pragma unroll
            for (int y = 0; y < RS_A; y++) vp += g_apos[(size_t)(y * NHNH + nh) * LA + row];
            vp /= g_sum_av[n];
        }
        s_sig[h] = 1.f / (1.f + expf(vp - spu));    // sigmoid(spu - vp)
    }
    __syncthreads();
    if (threadIdx.x == 0) {
        float prob = 0.f;
#pragma unroll
        for (int hh = 0; hh < HH; hh++) prob += s_sig[hh];
        prob *= (1.f / HH);
        float* o = out + n * OSTR;
        if (vside) {
            o[row] = prob;
            float uu = u_v[n * LV + row];
            o[3616 + row] = (uu < prob) ? 0.f : n_attn_av[n * LV + row];
        } else {
            o[1568 + row] = prob;
            float uu = u_a[n * LA + row];
            o[5184 + row] = (uu < prob) ? 0.f : n_attn_va[n * LA + row];
        }
    }
}

extern "C" void kernel_launch(void* const* d_in, const int* in_sizes, int n_in,
                              void* d_out, int out_size) {
    const float* pos_v_q   = (const float*)d_in[0];
    const float* pos_v_k   = (const float*)d_in[1];
    const float* pos_a_q   = (const float*)d_in[2];
    const float* pos_a_k   = (const float*)d_in[3];
    const float* cross_av  = (const float*)d_in[4];
    const float* cross_va  = (const float*)d_in[5];
    const float* n_attn_av = (const float*)d_in[6];
    const float* n_attn_va = (const float*)d_in[7];
    const float* spu_a_cls = (const float*)d_in[8];
    const float* spu_v_cls = (const float*)d_in[9];
    const float* u_v       = (const float*)d_in[10];
    const float* u_a       = (const float*)d_in[11];
    const int*   ids_v     = (const int*)d_in[12];
    const int*   ids_a     = (const int*)d_in[13];
    float* out = (float*)d_out;

    k0_prep<<<NN, 512>>>(n_attn_av, n_attn_va, ids_v, ids_a, out);
    k12_stream<<<K1_BLOCKS + K2_BLOCKS, 256>>>(cross_av, cross_va, ids_a, ids_v);
    k3_cls<<<dim3(NHNH, 2), 1024>>>(pos_v_q, pos_a_q, ids_v, ids_a, out);
    k45_prob<<<dim3(NCV + NCA, NN), 384>>>(pos_v_k, pos_a_k, spu_a_cls, spu_v_cls,
                                           ids_v, ids_a, u_v, u_a,
                                           n_attn_av, n_attn_va, out);
}

// round 13
// speedup vs baseline: 1.0512x; 1.0512x over previous
#include <cuda_runtime.h>
#include <math.h>

#define NN 8
#define HH 12
#define DHD 64
#define LV 1568
#define LA 512
#define NCV 392
#define NCA 256
#define NHNH (NN*HH)          // 96
#define OSTR 5696             // output row stride
#define RS_V 8
#define RS_A 8
#define SCALEF 0.125f

#define K1_BLOCKS (2 * RS_V * NHNH)   // 1536
#define K2_BLOCKS (RS_A * NHNH)       // 768
#define K3_BLOCKS (2 * NHNH)          // 192
#define CH_V 13                        // ceil(392/32)
#define CH_A 8                         // 256/32
#define CHUNK 32

// ---- scratch (device globals; no allocation allowed) ----
__device__ float g_w_av[NN * NCV];
__device__ float g_w_va[NN * NCA];
__device__ float g_sum_av[NN];
__device__ float g_sum_va[NN];
__device__ float g_vpos[RS_V * NHNH * LV];
__device__ float g_apos[RS_A * NHNH * LA];

// K0: gather weights, sums, fill output defaults
__global__ void k0_prep(const float* __restrict__ n_attn_av,
                        const float* __restrict__ n_attn_va,
                        const int* __restrict__ ids_v,
                        const int* __restrict__ ids_a,
                        float* __restrict__ out) {
    int n = blockIdx.x;
    int t = threadIdx.x;             // 512 threads
    __shared__ float red[512];

    float wv = 0.f;
    if (t < NCV) {
        int p = ids_v[n * LV + t];
        wv = n_attn_av[n * LV + p];
        g_w_av[n * NCV + t] = wv;
    }
    red[t] = wv;
    __syncthreads();
    for (int s = 256; s > 0; s >>= 1) {
        if (t < s) red[t] += red[t + s];
        __syncthreads();
    }
    if (t == 0) g_sum_av[n] = red[0];
    __syncthreads();

    float wa = 0.f;
    if (t < NCA) {
        int p = ids_a[n * LA + t];
        wa = n_attn_va[n * LA + p];
        g_w_va[n * NCA + t] = wa;
    }
    red[t] = wa;
    __syncthreads();
    for (int s = 256; s > 0; s >>= 1) {
        if (t < s) red[t] += red[t + s];
        __syncthreads();
    }
    if (t == 0) g_sum_va[n] = red[0];

    float* o = out + n * OSTR;
    for (int i = t; i < LV + LA; i += 512) o[i] = 0.f;
    for (int i = t; i < LV; i += 512) o[3616 + i] = n_attn_av[n * LV + i];
    for (int i = t; i < LA; i += 512) o[5184 + i] = n_attn_va[n * LA + i];
}

// KBIG: three block families in one launch (all depend only on k0):
//  [0, K1_BLOCKS)                 : v_pos partials from cross_av (float4 lanes)
//  [K1_BLOCKS, +K2_BLOCKS)        : a_pos partials from cross_va (float2 lanes)
//  [K1+K2, +K3_BLOCKS)            : cls weighted means (4 sub-groups x 64 lanes)
__global__ void kbig(const float* __restrict__ cross_av,
                     const float* __restrict__ cross_va,
                     const float* __restrict__ pos_v_q,
                     const float* __restrict__ pos_a_q,
                     const int* __restrict__ ids_a,
                     const int* __restrict__ ids_v,
                     float* __restrict__ out) {
    const int bid = blockIdx.x;
    const int t = threadIdx.x;   // 256
    __shared__ __align__(16) char smem_raw[4608];

    if (bid < K1_BLOCKS) {
        int* ridx = (int*)smem_raw;                 // 32
        float* rw = (float*)(smem_raw + 128);       // 32
        const int x = bid & 1;
        const int y = (bid >> 1) & (RS_V - 1);
        const int nh = bid >> 4;
        const int n = nh / HH;
        const int g = x * 256 + t;
        const int RPB = NCA / RS_V;                 // 32

        if (t < RPB) {
            int a = y * RPB + t;
            ridx[t] = ids_a[n * LA + a];
            rw[t]   = g_w_va[n * NCA + a];
        }
        __syncthreads();
        if (g >= LV / 4) return;

        float4 acc = make_float4(0.f, 0.f, 0.f, 0.f);
        const float4* base = (const float4*)cross_av;
        const size_t nhbase = (size_t)nh * LA * (LV / 4);
#pragma unroll 8
        for (int a = 0; a < RPB; a++) {
            float w = rw[a];
            float4 v = __ldg(base + nhbase + (size_t)ridx[a] * (LV / 4) + g);
            acc.x += w * v.x; acc.y += w * v.y; acc.z += w * v.z; acc.w += w * v.w;
        }
        ((float4*)g_vpos)[(size_t)(y * NHNH + nh) * (LV / 4) + g] = acc;
    } else if (bid < K1_BLOCKS + K2_BLOCKS) {
        int* ridx = (int*)smem_raw;                 // 49
        float* rw = (float*)(smem_raw + 256);       // 49
        const int b2 = bid - K1_BLOCKS;
        const int y = b2 & (RS_A - 1);
        const int nh = b2 >> 3;
        const int n = nh / HH;
        const int RPB = NCV / RS_A;                 // 49

        if (t < RPB) {
            int v = y * RPB + t;
            ridx[t] = ids_v[n * LV + v];
            rw[t]   = g_w_av[n * NCV + v];
        }
        __syncthreads();

        float2 acc = make_float2(0.f, 0.f);
        const float2* base = (const float2*)cross_va;
        const size_t nhbase = (size_t)nh * LV * (LA / 2);
#pragma unroll 7
        for (int a = 0; a < RPB; a++) {
            float w = rw[a];
            float2 v = __ldg(base + nhbase + (size_t)ridx[a] * (LA / 2) + t);
            acc.x += w * v.x; acc.y += w * v.y;
        }
        ((float2*)g_apos)[(size_t)(y * NHNH + nh) * (LA / 2) + t] = acc;
    } else {
        // cls: weighted mean over gathered rows of pos_*_q
        int* ridx = (int*)smem_raw;                       // up to 392 ints
        float* rw = (float*)(smem_raw + 1600);            // up to 392 floats
        float* part = (float*)(smem_raw + 3200);          // 4*64 floats
        const int b3 = bid - (K1_BLOCKS + K2_BLOCKS);
        const int nh = b3 >> 1;
        const bool vside = (b3 & 1) == 0;
        const int n = nh / HH;
        const int h = nh % HH;
        const int d = t & 63;
        const int sub = t >> 6;   // 0..3

        const int cnt = vside ? NCV : NCA;
        const int L = vside ? LV : LA;
        const int* ids = vside ? ids_v : ids_a;
        const float* wsrc = vside ? (g_w_av + n * NCV) : (g_w_va + n * NCA);
        const float* q = vside ? pos_v_q : pos_a_q;

        for (int i = t; i < cnt; i += 256) {
            ridx[i] = ids[n * L + i];
            rw[i]   = wsrc[i];
        }
        __syncthreads();

        float acc = 0.f;
        const float* basep = q + (size_t)nh * L * DHD;
#pragma unroll 8
        for (int i = sub; i < cnt; i += 4)
            acc += __ldg(basep + (size_t)ridx[i] * DHD + d) * rw[i];

        part[sub * DHD + d] = acc;
        __syncthreads();

        if (sub == 0) {
            float tot = acc + part[DHD + d] + part[2 * DHD + d] + part[3 * DHD + d];
            const float su = vside ? g_sum_av[n] : g_sum_va[n];
            const int off = vside ? 2080 : 2848;
            out[n * OSTR + off + h * DHD + d] = tot / su;
        }
    }
}

// KP: per-token prob, chunked. grid (CH_V+CH_A, NN), 384 threads = 12 warps (one per head).
// cls held in registers per warp; the 8 vpos/apos partials are folded into the same
// warp reduction via lanes 0..7 so (spu - vp) comes out of one 5-shfl reduce.
__global__ void kp_prob(const float* __restrict__ pos_v_k,
                        const float* __restrict__ pos_a_k,
                        const float* __restrict__ spu_a_cls,
                        const float* __restrict__ spu_v_cls,
                        const int* __restrict__ ids_v,
                        const int* __restrict__ ids_a,
                        const float* __restrict__ u_v,
                        const float* __restrict__ u_a,
                        const float* __restrict__ n_attn_av,
                        const float* __restrict__ n_attn_va,
                        float* __restrict__ out) {
    const int chunk = blockIdx.x;
    const int n = blockIdx.y;
    const bool vside = (chunk < CH_V);
    const int base = vside ? chunk * CHUNK : (chunk - CH_V) * CHUNK;
    const int cnt = vside ? min(CHUNK, NCV - base) : CHUNK;

    const int L = vside ? LV : LA;
    const int* ids = vside ? ids_v : ids_a;
    const float* kk = vside ? pos_v_k : pos_a_k;
    const float* cls = vside ? spu_a_cls : spu_v_cls;
    const float* gpos = vside ? g_vpos : g_apos;

    const int t = threadIdx.x;
    const int h = t >> 5;
    const int lane = t & 31;
    const int nh = n * HH + h;

    __shared__ int s_rows[CHUNK];
    __shared__ float s_sig[HH * CHUNK];

    if (t < CHUNK) s_rows[t] = (t < cnt) ? ids[n * L + base + t] : 0;

    const float2 c2 = __ldg((const float2*)(cls + (size_t)nh * DHD) + lane);
    const float inv = vside ? (1.f / g_sum_va[n]) : (1.f / g_sum_av[n]);
    __syncthreads();

#pragma unroll 4
    for (int tok = 0; tok < cnt; tok++) {
        const int row = s_rows[tok];
        float2 a2 = __ldg((const float2*)(kk + ((size_t)nh * L + row) * DHD) + lane);
        float val = (a2.x * c2.x + a2.y * c2.y) * SCALEF;
        if (lane < 8)
            val -= __ldg(&gpos[(size_t)(lane * NHNH + nh) * L + row]) * inv;
#pragma unroll
        for (int s = 16; s > 0; s >>= 1) val += __shfl_xor_sync(0xffffffff, val, s);
        if (lane == 0)
            s_sig[h * CHUNK + tok] = 1.f / (1.f + expf(-val));   // sigmoid(spu - vp)
    }
    __syncthreads();

    if (t < cnt) {
        float prob = 0.f;
#pragma unroll
        for (int hh = 0; hh < HH; hh++) prob += s_sig[hh * CHUNK + t];
        prob *= (1.f / HH);
        const int row = s_rows[t];
        float* o = out + n * OSTR;
        if (vside) {
            o[row] = prob;
            float uu = u_v[n * LV + row];
            o[3616 + row] = (uu < prob) ? 0.f : n_attn_av[n * LV + row];
        } else {
            o[1568 + row] = prob;
            float uu = u_a[n * LA + row];
            o[5184 + row] = (uu < prob) ? 0.f : n_attn_va[n * LA + row];
        }
    }
}

extern "C" void kernel_launch(void* const* d_in, const int* in_sizes, int n_in,
                              void* d_out, int out_size) {
    const float* pos_v_q   = (const float*)d_in[0];
    const float* pos_v_k   = (const float*)d_in[1];
    const float* pos_a_q   = (const float*)d_in[2];
    const float* pos_a_k   = (const float*)d_in[3];
    const float* cross_av  = (const float*)d_in[4];
    const float* cross_va  = (const float*)d_in[5];
    const float* n_attn_av = (const float*)d_in[6];
    const float* n_attn_va = (const float*)d_in[7];
    const float* spu_a_cls = (const float*)d_in[8];
    const float* spu_v_cls = (const float*)d_in[9];
    const float* u_v       = (const float*)d_in[10];
    const float* u_a       = (const float*)d_in[11];
    const int*   ids_v     = (const int*)d_in[12];
    const int*   ids_a     = (const int*)d_in[13];
    float* out = (float*)d_out;

    k0_prep<<<NN, 512>>>(n_attn_av, n_attn_va, ids_v, ids_a, out);
    kbig<<<K1_BLOCKS + K2_BLOCKS + K3_BLOCKS, 256>>>(cross_av, cross_va,
                                                     pos_v_q, pos_a_q,
                                                     ids_a, ids_v, out);
    kp_prob<<<dim3(CH_V + CH_A, NN), 384>>>(pos_v_k, pos_a_k, spu_a_cls, spu_v_cls,
                                            ids_v, ids_a, u_v, u_a,
                                            n_attn_av, n_attn_va, out);
}

// round 14
// speedup vs baseline: 1.0875x; 1.0345x over previous
#include <cuda_runtime.h>
#include <math.h>

#define NN 8
#define HH 12
#define DHD 64
#define LV 1568
#define LA 512
#define NCV 392
#define NCA 256
#define NHNH (NN*HH)          // 96
#define OSTR 5696             // output row stride
#define RS_V 8
#define RS_A 8
#define SCALEF 0.125f

#define K1_BLOCKS (2 * RS_V * NHNH)   // 1536
#define K2_BLOCKS (RS_A * NHNH)       // 768
#define K3_BLOCKS (2 * NHNH)          // 192
#define SUM_BLOCKS NN                 // 8
#define FILL_BLOCKS (4 * NN)          // 32
#define CH_V 13                        // ceil(392/32)
#define CH_A 8                         // 256/32
#define CHUNK 32

// ---- scratch (device globals; no allocation allowed) ----
__device__ float g_sum_av[NN];
__device__ float g_sum_va[NN];
__device__ float g_vpos[RS_V * NHNH * LV];
__device__ float g_apos[RS_A * NHNH * LA];

// KBIG: five block families, all depending only on kernel inputs:
//  [0, K1)            : v_pos partials from cross_av (float4 lanes), weights gathered direct
//  [K1, +K2)          : a_pos partials from cross_va (float2 lanes), weights gathered direct
//  [+K3)              : cls weighted means (in-block weight gather + sum)
//  [+SUM)             : g_sum_av / g_sum_va for kp
//  [+FILL)            : output defaults (prob=0, prune=n_attn)
__global__ void kbig(const float* __restrict__ cross_av,
                     const float* __restrict__ cross_va,
                     const float* __restrict__ pos_v_q,
                     const float* __restrict__ pos_a_q,
                     const int* __restrict__ ids_a,
                     const int* __restrict__ ids_v,
                     const float* __restrict__ n_attn_av,
                     const float* __restrict__ n_attn_va,
                     float* __restrict__ out) {
    const int bid = blockIdx.x;
    const int t = threadIdx.x;   // 256
    __shared__ __align__(16) char smem_raw[4608];

    if (bid < K1_BLOCKS) {
        int* ridx = (int*)smem_raw;                 // 32
        float* rw = (float*)(smem_raw + 128);       // 32
        const int x = bid & 1;
        const int y = (bid >> 1) & (RS_V - 1);
        const int nh = bid >> 4;
        const int n = nh / HH;
        const int g = x * 256 + t;
        const int RPB = NCA / RS_V;                 // 32

        if (t < RPB) {
            int a = y * RPB + t;
            int id = ids_a[n * LA + a];
            ridx[t] = id;
            rw[t]   = n_attn_va[n * LA + id];
        }
        __syncthreads();
        if (g >= LV / 4) return;

        float4 acc = make_float4(0.f, 0.f, 0.f, 0.f);
        const float4* base = (const float4*)cross_av;
        const size_t nhbase = (size_t)nh * LA * (LV / 4);
#pragma unroll 8
        for (int a = 0; a < RPB; a++) {
            float w = rw[a];
            float4 v = __ldg(base + nhbase + (size_t)ridx[a] * (LV / 4) + g);
            acc.x += w * v.x; acc.y += w * v.y; acc.z += w * v.z; acc.w += w * v.w;
        }
        ((float4*)g_vpos)[(size_t)(y * NHNH + nh) * (LV / 4) + g] = acc;
    } else if (bid < K1_BLOCKS + K2_BLOCKS) {
        int* ridx = (int*)smem_raw;                 // 49
        float* rw = (float*)(smem_raw + 256);       // 49
        const int b2 = bid - K1_BLOCKS;
        const int y = b2 & (RS_A - 1);
        const int nh = b2 >> 3;
        const int n = nh / HH;
        const int RPB = NCV / RS_A;                 // 49

        if (t < RPB) {
            int v = y * RPB + t;
            int id = ids_v[n * LV + v];
            ridx[t] = id;
            rw[t]   = n_attn_av[n * LV + id];
        }
        __syncthreads();

        float2 acc = make_float2(0.f, 0.f);
        const float2* base = (const float2*)cross_va;
        const size_t nhbase = (size_t)nh * LV * (LA / 2);
#pragma unroll 7
        for (int a = 0; a < RPB; a++) {
            float w = rw[a];
            float2 v = __ldg(base + nhbase + (size_t)ridx[a] * (LA / 2) + t);
            acc.x += w * v.x; acc.y += w * v.y;
        }
        ((float2*)g_apos)[(size_t)(y * NHNH + nh) * (LA / 2) + t] = acc;
    } else if (bid < K1_BLOCKS + K2_BLOCKS + K3_BLOCKS) {
        // cls: weighted mean over gathered rows of pos_*_q (in-block weight sum)
        int* ridx = (int*)smem_raw;                       // up to 392 ints
        float* rw = (float*)(smem_raw + 1600);            // up to 392 floats
        float* part = (float*)(smem_raw + 3200);          // 4*64 floats
        float* wred = (float*)(smem_raw + 4224);          // 8 warp sums + 1 total
        const int b3 = bid - (K1_BLOCKS + K2_BLOCKS);
        const int nh = b3 >> 1;
        const bool vside = (b3 & 1) == 0;
        const int n = nh / HH;
        const int h = nh % HH;
        const int d = t & 63;
        const int sub = t >> 6;   // 0..3

        const int cnt = vside ? NCV : NCA;
        const int L = vside ? LV : LA;
        const int* ids = vside ? ids_v : ids_a;
        const float* attn = vside ? n_attn_av : n_attn_va;
        const float* q = vside ? pos_v_q : pos_a_q;

        float lsum = 0.f;
        for (int i = t; i < cnt; i += 256) {
            int id = ids[n * L + i];
            float w = attn[n * L + id];
            ridx[i] = id;
            rw[i]   = w;
            lsum += w;
        }
#pragma unroll
        for (int s = 16; s > 0; s >>= 1) lsum += __shfl_xor_sync(0xffffffff, lsum, s);
        if ((t & 31) == 0) wred[t >> 5] = lsum;
        __syncthreads();

        float acc = 0.f;
        const float* basep = q + (size_t)nh * L * DHD;
#pragma unroll 8
        for (int i = sub; i < cnt; i += 4)
            acc += __ldg(basep + (size_t)ridx[i] * DHD + d) * rw[i];

        part[sub * DHD + d] = acc;
        __syncthreads();

        if (sub == 0) {
            float tot = acc + part[DHD + d] + part[2 * DHD + d] + part[3 * DHD + d];
            float su = 0.f;
#pragma unroll
            for (int w8 = 0; w8 < 8; w8++) su += wred[w8];
            const int off = vside ? 2080 : 2848;
            out[n * OSTR + off + h * DHD + d] = tot / su;
        }
    } else if (bid < K1_BLOCKS + K2_BLOCKS + K3_BLOCKS + SUM_BLOCKS) {
        // sums of gathered weights for kp
        float* red = (float*)smem_raw;   // 256 floats
        const int n = bid - (K1_BLOCKS + K2_BLOCKS + K3_BLOCKS);

        float sv = 0.f;
        for (int i = t; i < NCV; i += 256) {
            int id = ids_v[n * LV + i];
            sv += n_attn_av[n * LV + id];
        }
        red[t] = sv;
        __syncthreads();
        for (int s = 128; s > 0; s >>= 1) {
            if (t < s) red[t] += red[t + s];
            __syncthreads();
        }
        if (t == 0) g_sum_av[n] = red[0];
        __syncthreads();

        float sa = 0.f;
        for (int i = t; i < NCA; i += 256) {
            int id = ids_a[n * LA + i];
            sa += n_attn_va[n * LA + id];
        }
        red[t] = sa;
        __syncthreads();
        for (int s = 128; s > 0; s >>= 1) {
            if (t < s) red[t] += red[t + s];
            __syncthreads();
        }
        if (t == 0) g_sum_va[n] = red[0];
    } else {
        // output defaults
        const int b5 = bid - (K1_BLOCKS + K2_BLOCKS + K3_BLOCKS + SUM_BLOCKS);
        const int n = b5 >> 2;
        const int p = b5 & 3;
        float* o = out + n * OSTR;
        for (int i = p * 256 + t; i < LV + LA; i += 1024) o[i] = 0.f;
        for (int i = p * 256 + t; i < LV; i += 1024) o[3616 + i] = n_attn_av[n * LV + i];
        for (int i = p * 256 + t; i < LA; i += 1024) o[5184 + i] = n_attn_va[n * LA + i];
    }
}

// KP: per-token prob, chunked. grid (CH_V+CH_A, NN), 384 threads = 12 warps (one per head).
__global__ void kp_prob(const float* __restrict__ pos_v_k,
                        const float* __restrict__ pos_a_k,
                        const float* __restrict__ spu_a_cls,
                        const float* __restrict__ spu_v_cls,
                        const int* __restrict__ ids_v,
                        const int* __restrict__ ids_a,
                        const float* __restrict__ u_v,
                        const float* __restrict__ u_a,
                        const float* __restrict__ n_attn_av,
                        const float* __restrict__ n_attn_va,
                        float* __restrict__ out) {
    const int chunk = blockIdx.x;
    const int n = blockIdx.y;
    const bool vside = (chunk < CH_V);
    const int base = vside ? chunk * CHUNK : (chunk - CH_V) * CHUNK;
    const int cnt = vside ? min(CHUNK, NCV - base) : CHUNK;

    const int L = vside ? LV : LA;
    const int* ids = vside ? ids_v : ids_a;
    const float* kk = vside ? pos_v_k : pos_a_k;
    const float* cls = vside ? spu_a_cls : spu_v_cls;
    const float* gpos = vside ? g_vpos : g_apos;

    const int t = threadIdx.x;
    const int h = t >> 5;
    const int lane = t & 31;
    const int nh = n * HH + h;

    __shared__ int s_rows[CHUNK];
    __shared__ float s_sig[HH * CHUNK];

    if (t < CHUNK) s_rows[t] = (t < cnt) ? ids[n * L + base + t] : 0;

    const float2 c2 = __ldg((const float2*)(cls + (size_t)nh * DHD) + lane);
    const float inv = vside ? (1.f / g_sum_va[n]) : (1.f / g_sum_av[n]);
    __syncthreads();

#pragma unroll 4
    for (int tok = 0; tok < cnt; tok++) {
        const int row = s_rows[tok];
        float2 a2 = __ldg((const float2*)(kk + ((size_t)nh * L + row) * DHD) + lane);
        float val = (a2.x * c2.x + a2.y * c2.y) * SCALEF;
        if (lane < 8)
            val -= __ldg(&gpos[(size_t)(lane * NHNH + nh) * L + row]) * inv;
#pragma unroll
        for (int s = 16; s > 0; s >>= 1) val += __shfl_xor_sync(0xffffffff, val, s);
        if (lane == 0)
            s_sig[h * CHUNK + tok] = 1.f / (1.f + expf(-val));   // sigmoid(spu - vp)
    }
    __syncthreads();

    if (t < cnt) {
        float prob = 0.f;
#pragma unroll
        for (int hh = 0; hh < HH; hh++) prob += s_sig[hh * CHUNK + t];
        prob *= (1.f / HH);
        const int row = s_rows[t];
        float* o = out + n * OSTR;
        if (vside) {
            o[row] = prob;
            float uu = u_v[n * LV + row];
            o[3616 + row] = (uu < prob) ? 0.f : n_attn_av[n * LV + row];
        } else {
            o[1568 + row] = prob;
            float uu = u_a[n * LA + row];
            o[5184 + row] = (uu < prob) ? 0.f : n_attn_va[n * LA + row];
        }
    }
}

extern "C" void kernel_launch(void* const* d_in, const int* in_sizes, int n_in,
                              void* d_out, int out_size) {
    const float* pos_v_q   = (const float*)d_in[0];
    const float* pos_v_k   = (const float*)d_in[1];
    const float* pos_a_q   = (const float*)d_in[2];
    const float* pos_a_k   = (const float*)d_in[3];
    const float* cross_av  = (const float*)d_in[4];
    const float* cross_va  = (const float*)d_in[5];
    const float* n_attn_av = (const float*)d_in[6];
    const float* n_attn_va = (const float*)d_in[7];
    const float* spu_a_cls = (const float*)d_in[8];
    const float* spu_v_cls = (const float*)d_in[9];
    const float* u_v       = (const float*)d_in[10];
    const float* u_a       = (const float*)d_in[11];
    const int*   ids_v     = (const int*)d_in[12];
    const int*   ids_a     = (const int*)d_in[13];
    float* out = (float*)d_out;

    kbig<<<K1_BLOCKS + K2_BLOCKS + K3_BLOCKS + SUM_BLOCKS + FILL_BLOCKS, 256>>>(
        cross_av, cross_va, pos_v_q, pos_a_q, ids_a, ids_v,
        n_attn_av, n_attn_va, out);
    kp_prob<<<dim3(CH_V + CH_A, NN), 384>>>(pos_v_k, pos_a_k, spu_a_cls, spu_v_cls,
                                            ids_v, ids_a, u_v, u_a,
                                            n_attn_av, n_attn_va, out);
}

// round 15
// speedup vs baseline: 1.3313x; 1.2242x over previous
#include <cuda_runtime.h>
#include <math.h>

#define NN 8
#define HH 12
#define DHD 64
#define LV 1568
#define LA 512
#define NCV 392
#define NCA 256
#define NHNH (NN*HH)          // 96
#define OSTR 5696             // output row stride
#define RS_V 8
#define RS_A 8
#define SCALEF 0.125f

#define K1_BLOCKS (2 * RS_V * NHNH)   // 1536
#define K2_BLOCKS (RS_A * NHNH)       // 768
#define K3_BLOCKS (2 * NHNH)          // 192
#define SUM_BLOCKS NN                 // 8
#define FILL_BLOCKS (4 * NN)          // 32
#define CHUNK 8
#define CH_V (NCV / CHUNK)            // 49 (exact)
#define CH_A (NCA / CHUNK)            // 32 (exact)

// ---- scratch (device globals; no allocation allowed) ----
__device__ float g_sum_av[NN];
__device__ float g_sum_va[NN];
__device__ float g_vpos[RS_V * NHNH * LV];
__device__ float g_apos[RS_A * NHNH * LA];

// KBIG: five block families, all depending only on kernel inputs:
//  [0, K1)            : v_pos partials from cross_av (float4 lanes), weights gathered direct
//  [K1, +K2)          : a_pos partials from cross_va (float2 lanes), weights gathered direct
//  [+K3)              : cls weighted means (in-block weight gather + sum)
//  [+SUM)             : g_sum_av / g_sum_va for kp
//  [+FILL)            : output defaults (prob=0, prune=n_attn)
__global__ void kbig(const float* __restrict__ cross_av,
                     const float* __restrict__ cross_va,
                     const float* __restrict__ pos_v_q,
                     const float* __restrict__ pos_a_q,
                     const int* __restrict__ ids_a,
                     const int* __restrict__ ids_v,
                     const float* __restrict__ n_attn_av,
                     const float* __restrict__ n_attn_va,
                     float* __restrict__ out) {
    const int bid = blockIdx.x;
    const int t = threadIdx.x;   // 256
    __shared__ __align__(16) char smem_raw[4608];

    if (bid < K1_BLOCKS) {
        int* ridx = (int*)smem_raw;                 // 32
        float* rw = (float*)(smem_raw + 128);       // 32
        const int x = bid & 1;
        const int y = (bid >> 1) & (RS_V - 1);
        const int nh = bid >> 4;
        const int n = nh / HH;
        const int g = x * 256 + t;
        const int RPB = NCA / RS_V;                 // 32

        if (t < RPB) {
            int a = y * RPB + t;
            int id = ids_a[n * LA + a];
            ridx[t] = id;
            rw[t]   = n_attn_va[n * LA + id];
        }
        __syncthreads();
        if (g >= LV / 4) return;

        float4 acc = make_float4(0.f, 0.f, 0.f, 0.f);
        const float4* base = (const float4*)cross_av;
        const size_t nhbase = (size_t)nh * LA * (LV / 4);
#pragma unroll 8
        for (int a = 0; a < RPB; a++) {
            float w = rw[a];
            float4 v = __ldg(base + nhbase + (size_t)ridx[a] * (LV / 4) + g);
            acc.x += w * v.x; acc.y += w * v.y; acc.z += w * v.z; acc.w += w * v.w;
        }
        ((float4*)g_vpos)[(size_t)(y * NHNH + nh) * (LV / 4) + g] = acc;
    } else if (bid < K1_BLOCKS + K2_BLOCKS) {
        int* ridx = (int*)smem_raw;                 // 49
        float* rw = (float*)(smem_raw + 256);       // 49
        const int b2 = bid - K1_BLOCKS;
        const int y = b2 & (RS_A - 1);
        const int nh = b2 >> 3;
        const int n = nh / HH;
        const int RPB = NCV / RS_A;                 // 49

        if (t < RPB) {
            int v = y * RPB + t;
            int id = ids_v[n * LV + v];
            ridx[t] = id;
            rw[t]   = n_attn_av[n * LV + id];
        }
        __syncthreads();

        float2 acc = make_float2(0.f, 0.f);
        const float2* base = (const float2*)cross_va;
        const size_t nhbase = (size_t)nh * LV * (LA / 2);
#pragma unroll 7
        for (int a = 0; a < RPB; a++) {
            float w = rw[a];
            float2 v = __ldg(base + nhbase + (size_t)ridx[a] * (LA / 2) + t);
            acc.x += w * v.x; acc.y += w * v.y;
        }
        ((float2*)g_apos)[(size_t)(y * NHNH + nh) * (LA / 2) + t] = acc;
    } else if (bid < K1_BLOCKS + K2_BLOCKS + K3_BLOCKS) {
        // cls: weighted mean over gathered rows of pos_*_q (in-block weight sum)
        int* ridx = (int*)smem_raw;                       // up to 392 ints
        float* rw = (float*)(smem_raw + 1600);            // up to 392 floats
        float* part = (float*)(smem_raw + 3200);          // 4*64 floats
        float* wred = (float*)(smem_raw + 4224);          // 8 warp sums
        const int b3 = bid - (K1_BLOCKS + K2_BLOCKS);
        const int nh = b3 >> 1;
        const bool vside = (b3 & 1) == 0;
        const int n = nh / HH;
        const int h = nh % HH;
        const int d = t & 63;
        const int sub = t >> 6;   // 0..3

        const int cnt = vside ? NCV : NCA;
        const int L = vside ? LV : LA;
        const int* ids = vside ? ids_v : ids_a;
        const float* attn = vside ? n_attn_av : n_attn_va;
        const float* q = vside ? pos_v_q : pos_a_q;

        float lsum = 0.f;
        for (int i = t; i < cnt; i += 256) {
            int id = ids[n * L + i];
            float w = attn[n * L + id];
            ridx[i] = id;
            rw[i]   = w;
            lsum += w;
        }
#pragma unroll
        for (int s = 16; s > 0; s >>= 1) lsum += __shfl_xor_sync(0xffffffff, lsum, s);
        if ((t & 31) == 0) wred[t >> 5] = lsum;
        __syncthreads();

        float acc = 0.f;
        const float* basep = q + (size_t)nh * L * DHD;
#pragma unroll 8
        for (int i = sub; i < cnt; i += 4)
            acc += __ldg(basep + (size_t)ridx[i] * DHD + d) * rw[i];

        part[sub * DHD + d] = acc;
        __syncthreads();

        if (sub == 0) {
            float tot = acc + part[DHD + d] + part[2 * DHD + d] + part[3 * DHD + d];
            float su = 0.f;
#pragma unroll
            for (int w8 = 0; w8 < 8; w8++) su += wred[w8];
            const int off = vside ? 2080 : 2848;
            out[n * OSTR + off + h * DHD + d] = tot / su;
        }
    } else if (bid < K1_BLOCKS + K2_BLOCKS + K3_BLOCKS + SUM_BLOCKS) {
        // sums of gathered weights for kp
        float* red = (float*)smem_raw;   // 256 floats
        const int n = bid - (K1_BLOCKS + K2_BLOCKS + K3_BLOCKS);

        float sv = 0.f;
        for (int i = t; i < NCV; i += 256) {
            int id = ids_v[n * LV + i];
            sv += n_attn_av[n * LV + id];
        }
        red[t] = sv;
        __syncthreads();
        for (int s = 128; s > 0; s >>= 1) {
            if (t < s) red[t] += red[t + s];
            __syncthreads();
        }
        if (t == 0) g_sum_av[n] = red[0];
        __syncthreads();

        float sa = 0.f;
        for (int i = t; i < NCA; i += 256) {
            int id = ids_a[n * LA + i];
            sa += n_attn_va[n * LA + id];
        }
        red[t] = sa;
        __syncthreads();
        for (int s = 128; s > 0; s >>= 1) {
            if (t < s) red[t] += red[t + s];
            __syncthreads();
        }
        if (t == 0) g_sum_va[n] = red[0];
    } else {
        // output defaults
        const int b5 = bid - (K1_BLOCKS + K2_BLOCKS + K3_BLOCKS + SUM_BLOCKS);
        const int n = b5 >> 2;
        const int p = b5 & 3;
        float* o = out + n * OSTR;
        for (int i = p * 256 + t; i < LV + LA; i += 1024) o[i] = 0.f;
        for (int i = p * 256 + t; i < LV; i += 1024) o[3616 + i] = n_attn_av[n * LV + i];
        for (int i = p * 256 + t; i < LA; i += 1024) o[5184 + i] = n_attn_va[n * LA + i];
    }
}

// KP: per-token prob. grid ((CH_V+CH_A), NN) = 648 blocks, 384 threads = 12 warps (one per head).
// CHUNK=8 tokens per block; all 8 K-row loads + 8 gpos partial loads issued before any
// reduction (MLP~16/warp), then 8 independent shfl-reduce chains.
__global__ void kp_prob(const float* __restrict__ pos_v_k,
                        const float* __restrict__ pos_a_k,
                        const float* __restrict__ spu_a_cls,
                        const float* __restrict__ spu_v_cls,
                        const int* __restrict__ ids_v,
                        const int* __restrict__ ids_a,
                        const float* __restrict__ u_v,
                        const float* __restrict__ u_a,
                        const float* __restrict__ n_attn_av,
                        const float* __restrict__ n_attn_va,
                        float* __restrict__ out) {
    const int chunk = blockIdx.x;
    const int n = blockIdx.y;
    const bool vside = (chunk < CH_V);
    const int base = (vside ? chunk : chunk - CH_V) * CHUNK;

    const int L = vside ? LV : LA;
    const int* ids = vside ? ids_v : ids_a;
    const float* kk = vside ? pos_v_k : pos_a_k;
    const float* cls = vside ? spu_a_cls : spu_v_cls;
    const float* gpos = vside ? g_vpos : g_apos;

    const int t = threadIdx.x;
    const int h = t >> 5;
    const int lane = t & 31;
    const int nh = n * HH + h;

    __shared__ int s_rows[CHUNK];
    __shared__ float s_sig[HH * CHUNK];

    if (t < CHUNK) s_rows[t] = ids[n * L + base + t];

    const float2 c2 = __ldg((const float2*)(cls + (size_t)nh * DHD) + lane);
    const float inv = vside ? (1.f / g_sum_va[n]) : (1.f / g_sum_av[n]);
    __syncthreads();

    // Phase 1: issue all loads (independent; high MLP)
    int rows[CHUNK];
    float2 a2[CHUNK];
    float gp[CHUNK];
    const float2* kbase = (const float2*)(kk + (size_t)nh * L * DHD);
#pragma unroll
    for (int tok = 0; tok < CHUNK; tok++) {
        rows[tok] = s_rows[tok];
        a2[tok] = __ldg(kbase + (size_t)rows[tok] * (DHD / 2) + lane);
        gp[tok] = (lane < 8) ? __ldg(&gpos[(size_t)(lane * NHNH + nh) * L + rows[tok]]) : 0.f;
    }

    // Phase 2: 8 independent reduce chains
#pragma unroll
    for (int tok = 0; tok < CHUNK; tok++) {
        float val = (a2[tok].x * c2.x + a2[tok].y * c2.y) * SCALEF - gp[tok] * inv;
#pragma unroll
        for (int s = 16; s > 0; s >>= 1) val += __shfl_xor_sync(0xffffffff, val, s);
        if (lane == 0)
            s_sig[h * CHUNK + tok] = 1.f / (1.f + __expf(-val));   // sigmoid(spu - vp)
    }
    __syncthreads();

    if (t < CHUNK) {
        float prob = 0.f;
#pragma unroll
        for (int hh = 0; hh < HH; hh++) prob += s_sig[hh * CHUNK + t];
        prob *= (1.f / HH);
        const int row = s_rows[t];
        float* o = out + n * OSTR;
        if (vside) {
            o[row] = prob;
            float uu = u_v[n * LV + row];
            o[3616 + row] = (uu < prob) ? 0.f : n_attn_av[n * LV + row];
        } else {
            o[1568 + row] = prob;
            float uu = u_a[n * LA + row];
            o[5184 + row] = (uu < prob) ? 0.f : n_attn_va[n * LA + row];
        }
    }
}

extern "C" void kernel_launch(void* const* d_in, const int* in_sizes, int n_in,
                              void* d_out, int out_size) {
    const float* pos_v_q   = (const float*)d_in[0];
    const float* pos_v_k   = (const float*)d_in[1];
    const float* pos_a_q   = (const float*)d_in[2];
    const float* pos_a_k   = (const float*)d_in[3];
    const float* cross_av  = (const float*)d_in[4];
    const float* cross_va  = (const float*)d_in[5];
    const float* n_attn_av = (const float*)d_in[6];
    const float* n_attn_va = (const float*)d_in[7];
    const float* spu_a_cls = (const float*)d_in[8];
    const float* spu_v_cls = (const float*)d_in[9];
    const float* u_v       = (const float*)d_in[10];
    const float* u_a       = (const float*)d_in[11];
    const int*   ids_v     = (const int*)d_in[12];
    const int*   ids_a     = (const int*)d_in[13];
    float* out = (float*)d_out;

    kbig<<<K1_BLOCKS + K2_BLOCKS + K3_BLOCKS + SUM_BLOCKS + FILL_BLOCKS, 256>>>(
        cross_av, cross_va, pos_v_q, pos_a_q, ids_a, ids_v,
        n_attn_av, n_attn_va, out);
    kp_prob<<<dim3(CH_V + CH_A, NN), 384>>>(pos_v_k, pos_a_k, spu_a_cls, spu_v_cls,
                                            ids_v, ids_a, u_v, u_a,
                                            n_attn_av, n_attn_va, out);
}